// round 12
// baseline (speedup 1.0000x reference)
#include <cuda_runtime.h>
#include <cuda_bf16.h>
#include <cstdint>
#include <math.h>

#define N_TOK 8192
#define C_DIM 1024
#define E_NUM 8
#define DFF_DIM 4096
#define HROWS (2 * N_TOK + 128)
#define ABUF 4096          // words per A stage buffer (2 slices * 128 rows * 16)
#define SMEM_DYN_BYTES (4 * ABUF * 2 * 4)   // A[2buf] + B[2buf] = 16384 words = 64KB

// ---------------- scratch (~270MB total — proven-passing level) ---------------
__device__ float g_h[HROWS * DFF_DIM];     // fp32 gelu(x@w1) rows, bucketed
__device__ int   g_counts[E_NUM];
__device__ int   g_offsets[E_NUM];
__device__ int   g_tok[E_NUM * N_TOK];
__device__ float g_wgt[E_NUM * N_TOK];

// ---------------- helpers -----------------------------------------------------
__device__ __forceinline__ void mma_bf16(float* d, const uint32_t* a, const uint32_t* b) {
    asm volatile(
        "mma.sync.aligned.m16n8k16.row.col.f32.bf16.bf16.f32 "
        "{%0,%1,%2,%3}, {%4,%5,%6,%7}, {%8,%9}, {%0,%1,%2,%3};"
        : "+f"(d[0]), "+f"(d[1]), "+f"(d[2]), "+f"(d[3])
        : "r"(a[0]), "r"(a[1]), "r"(a[2]), "r"(a[3]), "r"(b[0]), "r"(b[1]));
}

// truncation split of a pair: hi = top 16 bits (exact trunc), lo = exact residual
__device__ __forceinline__ void tsplit2(float vx, float vy, uint32_t& hi, uint32_t& lo) {
    uint32_t ax = __float_as_uint(vx), ay = __float_as_uint(vy);
    float lx = vx - __uint_as_float(ax & 0xFFFF0000u);
    float ly = vy - __uint_as_float(ay & 0xFFFF0000u);
    hi = __byte_perm(ax, ay, 0x7632);
    lo = __byte_perm(__float_as_uint(lx), __float_as_uint(ly), 0x7632);
}

__device__ __forceinline__ float gelu_exact(float v) {
    return 0.5f * v * (1.0f + erff(v * 0.70710678118654752f));
}

// ---------------- small kernels (verbatim) -------------------------------------
__global__ void zero_counts_kernel() {
    if (threadIdx.x < E_NUM) g_counts[threadIdx.x] = 0;
}
__global__ void zero_out_kernel(float* out, int n) {
    for (int i = blockIdx.x * blockDim.x + threadIdx.x; i < n; i += gridDim.x * blockDim.x)
        out[i] = 0.0f;
}
__global__ void offsets_kernel() {
    int run = 0;
    for (int e = 0; e < E_NUM; e++) { g_offsets[e] = run; run += g_counts[e]; }
}

__global__ void router_kernel(const float* __restrict__ x,
                              const float* __restrict__ rw,
                              const float* __restrict__ rb) {
    int t = blockIdx.x;
    int tid = threadIdx.x;
    __shared__ float red[128][E_NUM];
    float acc[E_NUM];
#pragma unroll
    for (int e = 0; e < E_NUM; e++) acc[e] = 0.0f;
    const float* xr = x + (size_t)t * C_DIM;
    for (int c = tid; c < C_DIM; c += 128) {
        float xv = xr[c];
        const float* w = &rw[c * E_NUM];
#pragma unroll
        for (int e = 0; e < E_NUM; e++) acc[e] += xv * w[e];
    }
#pragma unroll
    for (int e = 0; e < E_NUM; e++) red[tid][e] = acc[e];
    __syncthreads();
    for (int s = 64; s > 0; s >>= 1) {
        if (tid < s) {
#pragma unroll
            for (int e = 0; e < E_NUM; e++) red[tid][e] += red[tid + s][e];
        }
        __syncthreads();
    }
    if (tid == 0) {
        float lg[E_NUM], p[E_NUM];
        float mx = -1e30f;
#pragma unroll
        for (int e = 0; e < E_NUM; e++) { lg[e] = red[0][e] + rb[e]; mx = fmaxf(mx, lg[e]); }
        float sum = 0.0f;
#pragma unroll
        for (int e = 0; e < E_NUM; e++) { p[e] = expf(lg[e] - mx); sum += p[e]; }
        float inv = 1.0f / sum;
#pragma unroll
        for (int e = 0; e < E_NUM; e++) p[e] *= inv;
        int i1 = 0;
#pragma unroll
        for (int e = 1; e < E_NUM; e++) if (p[e] > p[i1]) i1 = e;
        int i2 = (i1 == 0) ? 1 : 0;
#pragma unroll
        for (int e = 0; e < E_NUM; e++) if (e != i1 && p[e] > p[i2]) i2 = e;
        int s1 = atomicAdd(&g_counts[i1], 1);
        g_tok[i1 * N_TOK + s1] = t;  g_wgt[i1 * N_TOK + s1] = p[i1];
        int s2 = atomicAdd(&g_counts[i2], 1);
        g_tok[i2 * N_TOK + s2] = t;  g_wgt[i2 * N_TOK + s2] = p[i2];
    }
}

// ---------------- HMMA GEMM: double-buffered smem + combined hi/lo layout ------
// CTA 128m x 128n x 32k-stage. 8 warps (2m x 4n), warp tile 64x32.
// Smem word layout (pitch 16/row): word (row*16 + 2*pos + {0:hi,1:lo}),
// pos(w) = (w&3)*2 + (w>>2). Fragment read = 1 uint4 -> {hi(2lc),lo(2lc),hi(2lc+1),lo(2lc+1)}.
// Pipeline per stage: LDG(s+1) -> compute(buf s&1) -> split+store(buf (s+1)&1) -> sync.
template <int KTOT, int NDIM, bool G1>
__global__ void __launch_bounds__(256, 1)
gemm_hmma(const float* __restrict__ A_g, const float* __restrict__ B_g,
          const float* __restrict__ bias_g, float* __restrict__ out) {
    extern __shared__ __align__(16) uint32_t sdyn[];
    uint32_t* sA = sdyn;                 // 2 buffers x 4096 words
    uint32_t* sB = sdyn + 2 * ABUF;      // 2 buffers x 4096 words
    __shared__ int   srow_s[128];
    __shared__ int   stok_s[128];
    __shared__ float swgt_s[128];

    int e = blockIdx.z;
    int cnt = g_counts[e];
    int m0 = blockIdx.y * 128;
    if (m0 >= cnt) return;
    int n0 = blockIdx.x * 128;
    int off = g_offsets[e];

    int tid = threadIdx.x, lane = tid & 31, wid = tid >> 5;
    int wm = wid >> 2, wn = wid & 3;
    int l4 = lane >> 2, lc = lane & 3;

    if (tid < 128) {
        int m = m0 + tid;
        int sr = 0, tk = 0; float wg = 0.0f;
        if (m < cnt) {
            tk = g_tok[e * N_TOK + m];
            wg = g_wgt[e * N_TOK + m];
            sr = G1 ? tk : (off + m);
        }
        srow_s[tid] = sr; stok_s[tid] = tk; swgt_s[tid] = wg;
    }
    __syncthreads();

    const float* Abase = G1 ? A_g : g_h;
    const float* Bp = B_g + (size_t)e * KTOT * NDIM + n0;
    const float* bias = bias_g + (size_t)e * NDIM + n0;

    // ---- staging assignments ----
    // A: pair prA = tid&15 (k = 2prA..2prA+1), slice = prA>>3, pos = f(prA&7); rows (tid>>4)+16i
    int prA = tid & 15;
    int slA = prA >> 3, wA = prA & 7;
    int posA = (wA & 3) * 2 + (wA >> 2);
    const float* aptr[8];
    int aws[8];
#pragma unroll
    for (int i = 0; i < 8; i++) {
        int r = (tid >> 4) + 16 * i;
        aptr[i] = Abase + (size_t)srow_s[r] * KTOT + 2 * prA;
        aws[i] = (slA * 128 + r) * 16 + 2 * posA;
    }
    // B: col nB = tid&127, pairs pk = (tid>>7)+2i
    int nB = tid & 127;
    const float* bptr[8];
    int bws[8];
#pragma unroll
    for (int i = 0; i < 8; i++) {
        int pk = (tid >> 7) + 2 * i;
        int slB = pk >> 3, wB = pk & 7;
        int posB = (wB & 3) * 2 + (wB >> 2);
        bptr[i] = Bp + (size_t)(2 * pk) * NDIM + nB;
        bws[i] = (slB * 128 + nB) * 16 + 2 * posB;
    }

    float acc[4][4][4];
#pragma unroll
    for (int a = 0; a < 4; a++)
#pragma unroll
        for (int b = 0; b < 4; b++)
#pragma unroll
            for (int c = 0; c < 4; c++) acc[a][b][c] = 0.0f;

    const int NS = KTOT / 32;
    float2 pa[8];
    float pbx[8], pby[8];

    // preamble: load + stage 0 into buffer 0
#pragma unroll
    for (int i = 0; i < 8; i++) pa[i] = *(const float2*)(aptr[i]);
#pragma unroll
    for (int i = 0; i < 8; i++) { pbx[i] = bptr[i][0]; pby[i] = bptr[i][NDIM]; }
#pragma unroll
    for (int i = 0; i < 8; i++) {
        uint32_t hi, lo;
        tsplit2(pa[i].x, pa[i].y, hi, lo);
        *(uint2*)&sA[aws[i]] = make_uint2(hi, lo);
    }
#pragma unroll
    for (int i = 0; i < 8; i++) {
        uint32_t hi, lo;
        tsplit2(pbx[i], pby[i], hi, lo);
        *(uint2*)&sB[bws[i]] = make_uint2(hi, lo);
    }
    __syncthreads();

    for (int s = 0; s < NS; s++) {
        // issue global loads for next stage (consumed after compute)
        if (s + 1 < NS) {
            size_t ka = (size_t)(s + 1) * 32;
#pragma unroll
            for (int i = 0; i < 8; i++) pa[i] = *(const float2*)(aptr[i] + ka);
            size_t kb = ka * NDIM;
#pragma unroll
            for (int i = 0; i < 8; i++) {
                pbx[i] = *(bptr[i] + kb);
                pby[i] = *(bptr[i] + kb + NDIM);
            }
        }

        // compute current stage
        const uint32_t* cA = sA + (s & 1) * ABUF;
        const uint32_t* cB = sB + (s & 1) * ABUF;
#pragma unroll
        for (int ks = 0; ks < 2; ks++) {
            uint32_t bhf[4][2], blf[4][2];
#pragma unroll
            for (int nt = 0; nt < 4; nt++) {
                int n = wn * 32 + nt * 8 + l4;
                uint4 v = *(const uint4*)&cB[(ks * 128 + n) * 16 + 4 * lc];
                bhf[nt][0] = v.x; blf[nt][0] = v.y;
                bhf[nt][1] = v.z; blf[nt][1] = v.w;
            }
            uint32_t ahf[4][4], alf[4][4];
#pragma unroll
            for (int mt = 0; mt < 4; mt++) {
                int r = wm * 64 + mt * 16 + l4;
                uint4 v0 = *(const uint4*)&cA[(ks * 128 + r) * 16 + 4 * lc];
                uint4 v1 = *(const uint4*)&cA[(ks * 128 + r + 8) * 16 + 4 * lc];
                ahf[mt][0] = v0.x; ahf[mt][1] = v1.x; ahf[mt][2] = v0.z; ahf[mt][3] = v1.z;
                alf[mt][0] = v0.y; alf[mt][1] = v1.y; alf[mt][2] = v0.w; alf[mt][3] = v1.w;
            }
#pragma unroll
            for (int mt = 0; mt < 4; mt++)
#pragma unroll
                for (int nt = 0; nt < 4; nt++)
                    mma_bf16(acc[mt][nt], ahf[mt], bhf[nt]);
#pragma unroll
            for (int mt = 0; mt < 4; mt++)
#pragma unroll
                for (int nt = 0; nt < 4; nt++)
                    mma_bf16(acc[mt][nt], ahf[mt], blf[nt]);
#pragma unroll
            for (int mt = 0; mt < 4; mt++)
#pragma unroll
                for (int nt = 0; nt < 4; nt++)
                    mma_bf16(acc[mt][nt], alf[mt], bhf[nt]);
        }

        // stage next buffer (hidden under next iteration's compute latency-wise)
        if (s + 1 < NS) {
            uint32_t* dA = sA + ((s + 1) & 1) * ABUF;
            uint32_t* dB = sB + ((s + 1) & 1) * ABUF;
#pragma unroll
            for (int i = 0; i < 8; i++) {
                uint32_t hi, lo;
                tsplit2(pa[i].x, pa[i].y, hi, lo);
                *(uint2*)&dA[aws[i]] = make_uint2(hi, lo);
            }
#pragma unroll
            for (int i = 0; i < 8; i++) {
                uint32_t hi, lo;
                tsplit2(pbx[i], pby[i], hi, lo);
                *(uint2*)&dB[bws[i]] = make_uint2(hi, lo);
            }
        }
        __syncthreads();
    }

    // ---- epilogue (verbatim) ----
#pragma unroll
    for (int mt = 0; mt < 4; mt++) {
#pragma unroll
        for (int half = 0; half < 2; half++) {
            int mrow = wm * 64 + mt * 16 + l4 + half * 8;
            if (m0 + mrow >= cnt) continue;
            if (G1) {
                float* hrow = g_h + (size_t)(off + m0 + mrow) * DFF_DIM + n0;
#pragma unroll
                for (int nt = 0; nt < 4; nt++) {
                    int c = wn * 32 + nt * 8 + lc * 2;
                    float v0 = gelu_exact(acc[mt][nt][half * 2 + 0] + bias[c]);
                    float v1 = gelu_exact(acc[mt][nt][half * 2 + 1] + bias[c + 1]);
                    *(float2*)(hrow + c) = make_float2(v0, v1);
                }
            } else {
                int tok = stok_s[mrow];
                float wgt = swgt_s[mrow];
                float* orow = out + (size_t)tok * C_DIM + n0;
#pragma unroll
                for (int nt = 0; nt < 4; nt++) {
                    int c = wn * 32 + nt * 8 + lc * 2;
                    atomicAdd(orow + c,     wgt * (acc[mt][nt][half * 2 + 0] + bias[c]));
                    atomicAdd(orow + c + 1, wgt * (acc[mt][nt][half * 2 + 1] + bias[c + 1]));
                }
            }
        }
    }
}

// ---------------- launch ------------------------------------------------------
extern "C" void kernel_launch(void* const* d_in, const int* in_sizes, int n_in,
                              void* d_out, int out_size) {
    const float* x  = (const float*)d_in[0];
    const float* rw = (const float*)d_in[1];
    const float* rb = (const float*)d_in[2];
    const float* w1 = (const float*)d_in[3];
    const float* b1 = (const float*)d_in[4];
    const float* w2 = (const float*)d_in[5];
    const float* b2 = (const float*)d_in[6];
    float* out = (float*)d_out;

    cudaFuncSetAttribute(gemm_hmma<C_DIM, DFF_DIM, true>,
                         cudaFuncAttributeMaxDynamicSharedMemorySize, SMEM_DYN_BYTES);
    cudaFuncSetAttribute(gemm_hmma<DFF_DIM, C_DIM, false>,
                         cudaFuncAttributeMaxDynamicSharedMemorySize, SMEM_DYN_BYTES);

    zero_counts_kernel<<<1, 32>>>();
    router_kernel<<<N_TOK, 128>>>(x, rw, rb);
    offsets_kernel<<<1, 1>>>();
    zero_out_kernel<<<512, 256>>>(out, N_TOK * C_DIM);

    {
        dim3 g(DFF_DIM / 128, N_TOK / 128, E_NUM);
        gemm_hmma<C_DIM, DFF_DIM, true><<<g, 256, SMEM_DYN_BYTES>>>(x, w1, b1, nullptr);
    }
    {
        dim3 g(C_DIM / 128, N_TOK / 128, E_NUM);
        gemm_hmma<DFF_DIM, C_DIM, false><<<g, 256, SMEM_DYN_BYTES>>>(nullptr, w2, b2, out);
    }
}

// round 13
// speedup vs baseline: 1.8494x; 1.8494x over previous
#include <cuda_runtime.h>
#include <cuda_bf16.h>
#include <cstdint>
#include <math.h>

#define N_TOK 8192
#define C_DIM 1024
#define E_NUM 8
#define DFF_DIM 4096
#define HROWS (2 * N_TOK + 128)

// dynamic smem layout (words): conflict-free round-10 pitches, double-buffered
//  sAh: 2 stages x 2048   @ 0
//  sAl: 2 stages x 2048   @ 4096
//  sBh: 2 stages x 2560   @ 8192
//  sBl: 2 stages x 2560   @ 13312
#define AW 2048
#define BW 2560
#define OFF_AL 4096
#define OFF_BH 8192
#define OFF_BL 13312
#define SMEM_DYN_BYTES ((OFF_BL + 2 * BW) * 4)   // 73728 B

// ---------------- scratch (~270MB total — proven-passing level) ---------------
__device__ float g_h[HROWS * DFF_DIM];     // fp32 gelu(x@w1) rows, bucketed
__device__ int   g_counts[E_NUM];
__device__ int   g_offsets[E_NUM];
__device__ int   g_tok[E_NUM * N_TOK];
__device__ float g_wgt[E_NUM * N_TOK];

// ---------------- helpers -----------------------------------------------------
__device__ __forceinline__ void mma_bf16(float* d, const uint32_t* a, const uint32_t* b) {
    asm volatile(
        "mma.sync.aligned.m16n8k16.row.col.f32.bf16.bf16.f32 "
        "{%0,%1,%2,%3}, {%4,%5,%6,%7}, {%8,%9}, {%0,%1,%2,%3};"
        : "+f"(d[0]), "+f"(d[1]), "+f"(d[2]), "+f"(d[3])
        : "r"(a[0]), "r"(a[1]), "r"(a[2]), "r"(a[3]), "r"(b[0]), "r"(b[1]));
}

// truncation split of a pair: hi = top 16 bits (exact trunc), lo = exact residual
__device__ __forceinline__ void tsplit2(float vx, float vy, uint32_t& hi, uint32_t& lo) {
    uint32_t ax = __float_as_uint(vx), ay = __float_as_uint(vy);
    float lx = vx - __uint_as_float(ax & 0xFFFF0000u);
    float ly = vy - __uint_as_float(ay & 0xFFFF0000u);
    hi = __byte_perm(ax, ay, 0x7632);
    lo = __byte_perm(__float_as_uint(lx), __float_as_uint(ly), 0x7632);
}

__device__ __forceinline__ float gelu_exact(float v) {
    return 0.5f * v * (1.0f + erff(v * 0.70710678118654752f));
}

// ---------------- small kernels (verbatim) -------------------------------------
__global__ void zero_counts_kernel() {
    if (threadIdx.x < E_NUM) g_counts[threadIdx.x] = 0;
}
__global__ void zero_out_kernel(float* out, int n) {
    for (int i = blockIdx.x * blockDim.x + threadIdx.x; i < n; i += gridDim.x * blockDim.x)
        out[i] = 0.0f;
}
__global__ void offsets_kernel() {
    int run = 0;
    for (int e = 0; e < E_NUM; e++) { g_offsets[e] = run; run += g_counts[e]; }
}

__global__ void router_kernel(const float* __restrict__ x,
                              const float* __restrict__ rw,
                              const float* __restrict__ rb) {
    int t = blockIdx.x;
    int tid = threadIdx.x;
    __shared__ float red[128][E_NUM];
    float acc[E_NUM];
#pragma unroll
    for (int e = 0; e < E_NUM; e++) acc[e] = 0.0f;
    const float* xr = x + (size_t)t * C_DIM;
    for (int c = tid; c < C_DIM; c += 128) {
        float xv = xr[c];
        const float* w = &rw[c * E_NUM];
#pragma unroll
        for (int e = 0; e < E_NUM; e++) acc[e] += xv * w[e];
    }
#pragma unroll
    for (int e = 0; e < E_NUM; e++) red[tid][e] = acc[e];
    __syncthreads();
    for (int s = 64; s > 0; s >>= 1) {
        if (tid < s) {
#pragma unroll
            for (int e = 0; e < E_NUM; e++) red[tid][e] += red[tid + s][e];
        }
        __syncthreads();
    }
    if (tid == 0) {
        float lg[E_NUM], p[E_NUM];
        float mx = -1e30f;
#pragma unroll
        for (int e = 0; e < E_NUM; e++) { lg[e] = red[0][e] + rb[e]; mx = fmaxf(mx, lg[e]); }
        float sum = 0.0f;
#pragma unroll
        for (int e = 0; e < E_NUM; e++) { p[e] = expf(lg[e] - mx); sum += p[e]; }
        float inv = 1.0f / sum;
#pragma unroll
        for (int e = 0; e < E_NUM; e++) p[e] *= inv;
        int i1 = 0;
#pragma unroll
        for (int e = 1; e < E_NUM; e++) if (p[e] > p[i1]) i1 = e;
        int i2 = (i1 == 0) ? 1 : 0;
#pragma unroll
        for (int e = 0; e < E_NUM; e++) if (e != i1 && p[e] > p[i2]) i2 = e;
        int s1 = atomicAdd(&g_counts[i1], 1);
        g_tok[i1 * N_TOK + s1] = t;  g_wgt[i1 * N_TOK + s1] = p[i1];
        int s2 = atomicAdd(&g_counts[i2], 1);
        g_tok[i2 * N_TOK + s2] = t;  g_wgt[i2 * N_TOK + s2] = p[i2];
    }
}

// ---------------- HMMA GEMM: round-10 layout + double-buffered stages ----------
// CTA 128m x 128n x 32k-stage. 8 warps (2m x 4n), warp tile 64x32.
// A smem: [stage][slice][row][8 words] pitch 8 (conflict-free per 16-lane phase)
// B smem: [stage][slice][n][8 words]  pitch 10 (conflict-free)
// Pipeline/stage: LDG(s+1) -> compute(buf s&1) -> split+store(buf (s+1)&1) -> sync.
template <int KTOT, int NDIM, bool G1>
__global__ void __launch_bounds__(256, 1)
gemm_hmma(const float* __restrict__ A_g, const float* __restrict__ B_g,
          const float* __restrict__ bias_g, float* __restrict__ out) {
    extern __shared__ __align__(16) uint32_t sdyn[];
    __shared__ int   srow_s[128];
    __shared__ int   stok_s[128];
    __shared__ float swgt_s[128];

    int e = blockIdx.z;
    int cnt = g_counts[e];
    int m0 = blockIdx.y * 128;
    if (m0 >= cnt) return;
    int n0 = blockIdx.x * 128;
    int off = g_offsets[e];

    int tid = threadIdx.x, lane = tid & 31, wid = tid >> 5;
    int wm = wid >> 2, wn = wid & 3;
    int l4 = lane >> 2, lc = lane & 3;

    if (tid < 128) {
        int m = m0 + tid;
        int sr = 0, tk = 0; float wg = 0.0f;
        if (m < cnt) {
            tk = g_tok[e * N_TOK + m];
            wg = g_wgt[e * N_TOK + m];
            sr = G1 ? tk : (off + m);
        }
        srow_s[tid] = sr; stok_s[tid] = tk; swgt_s[tid] = wg;
    }
    __syncthreads();

    const float* Abase = G1 ? A_g : g_h;
    const float* Bp = B_g + (size_t)e * KTOT * NDIM + n0;
    const float* bias = bias_g + (size_t)e * NDIM + n0;

    // ---- staging assignments (round-10 verbatim) ----
    int prA = tid & 15;
    int slA = prA >> 3, wA = prA & 7;
    int posA = (wA & 3) * 2 + (wA >> 2);
    const float* aptr[8];
    int aws[8];
#pragma unroll
    for (int i = 0; i < 8; i++) {
        int r = (tid >> 4) + 16 * i;
        aptr[i] = Abase + (size_t)srow_s[r] * KTOT + 2 * prA;
        aws[i] = (slA * 128 + r) * 8 + posA;
    }
    int nB = tid & 127;
    const float* bptr[8];
    int bws[8];
#pragma unroll
    for (int i = 0; i < 8; i++) {
        int pk = (tid >> 7) + 2 * i;
        int slB = pk >> 3, wB = pk & 7;
        int posB = (wB & 3) * 2 + (wB >> 2);
        bptr[i] = Bp + (size_t)(2 * pk) * NDIM + nB;
        bws[i] = (slB * 128 + nB) * 10 + posB;
    }

    float acc[4][4][4];
#pragma unroll
    for (int a = 0; a < 4; a++)
#pragma unroll
        for (int b = 0; b < 4; b++)
#pragma unroll
            for (int c = 0; c < 4; c++) acc[a][b][c] = 0.0f;

    const int NS = KTOT / 32;
    float2 pa[8];
    float pbx[8], pby[8];

    // preamble: load + stage 0 into buffer 0
#pragma unroll
    for (int i = 0; i < 8; i++) pa[i] = *(const float2*)(aptr[i]);
#pragma unroll
    for (int i = 0; i < 8; i++) { pbx[i] = bptr[i][0]; pby[i] = bptr[i][NDIM]; }
#pragma unroll
    for (int i = 0; i < 8; i++) {
        uint32_t hi, lo;
        tsplit2(pa[i].x, pa[i].y, hi, lo);
        sdyn[aws[i]] = hi;
        sdyn[OFF_AL + aws[i]] = lo;
    }
#pragma unroll
    for (int i = 0; i < 8; i++) {
        uint32_t hi, lo;
        tsplit2(pbx[i], pby[i], hi, lo);
        sdyn[OFF_BH + bws[i]] = hi;
        sdyn[OFF_BL + bws[i]] = lo;
    }
    __syncthreads();

    for (int s = 0; s < NS; s++) {
        // global loads for next stage
        if (s + 1 < NS) {
            size_t ka = (size_t)(s + 1) * 32;
#pragma unroll
            for (int i = 0; i < 8; i++) pa[i] = *(const float2*)(aptr[i] + ka);
            size_t kb = ka * NDIM;
#pragma unroll
            for (int i = 0; i < 8; i++) {
                pbx[i] = *(bptr[i] + kb);
                pby[i] = *(bptr[i] + kb + NDIM);
            }
        }

        // compute current stage
        const uint32_t* cAh = sdyn + (s & 1) * AW;
        const uint32_t* cAl = sdyn + OFF_AL + (s & 1) * AW;
        const uint32_t* cBh = sdyn + OFF_BH + (s & 1) * BW;
        const uint32_t* cBl = sdyn + OFF_BL + (s & 1) * BW;
#pragma unroll
        for (int ks = 0; ks < 2; ks++) {
            uint32_t bhf[4][2], blf[4][2];
#pragma unroll
            for (int nt = 0; nt < 4; nt++) {
                int n = wn * 32 + nt * 8 + l4;
                int wbi = (ks * 128 + n) * 10 + 2 * lc;
                uint2 h = *(const uint2*)&cBh[wbi];
                uint2 l = *(const uint2*)&cBl[wbi];
                bhf[nt][0] = h.x; bhf[nt][1] = h.y;
                blf[nt][0] = l.x; blf[nt][1] = l.y;
            }
            uint32_t ahf[4][4], alf[4][4];
#pragma unroll
            for (int mt = 0; mt < 4; mt++) {
                int r = wm * 64 + mt * 16 + l4;
                int wa0 = (ks * 128 + r) * 8 + 2 * lc;
                int wa1 = (ks * 128 + r + 8) * 8 + 2 * lc;
                uint2 h0 = *(const uint2*)&cAh[wa0];
                uint2 h1 = *(const uint2*)&cAh[wa1];
                uint2 l0 = *(const uint2*)&cAl[wa0];
                uint2 l1 = *(const uint2*)&cAl[wa1];
                ahf[mt][0] = h0.x; ahf[mt][1] = h1.x; ahf[mt][2] = h0.y; ahf[mt][3] = h1.y;
                alf[mt][0] = l0.x; alf[mt][1] = l1.x; alf[mt][2] = l0.y; alf[mt][3] = l1.y;
            }
#pragma unroll
            for (int mt = 0; mt < 4; mt++)
#pragma unroll
                for (int nt = 0; nt < 4; nt++)
                    mma_bf16(acc[mt][nt], ahf[mt], bhf[nt]);
#pragma unroll
            for (int mt = 0; mt < 4; mt++)
#pragma unroll
                for (int nt = 0; nt < 4; nt++)
                    mma_bf16(acc[mt][nt], ahf[mt], blf[nt]);
#pragma unroll
            for (int mt = 0; mt < 4; mt++)
#pragma unroll
                for (int nt = 0; nt < 4; nt++)
                    mma_bf16(acc[mt][nt], alf[mt], bhf[nt]);
        }

        // stage next buffer (overlaps MMA drain)
        if (s + 1 < NS) {
            uint32_t* dAh = sdyn + ((s + 1) & 1) * AW;
            uint32_t* dAl = sdyn + OFF_AL + ((s + 1) & 1) * AW;
            uint32_t* dBh = sdyn + OFF_BH + ((s + 1) & 1) * BW;
            uint32_t* dBl = sdyn + OFF_BL + ((s + 1) & 1) * BW;
#pragma unroll
            for (int i = 0; i < 8; i++) {
                uint32_t hi, lo;
                tsplit2(pa[i].x, pa[i].y, hi, lo);
                dAh[aws[i]] = hi;
                dAl[aws[i]] = lo;
            }
#pragma unroll
            for (int i = 0; i < 8; i++) {
                uint32_t hi, lo;
                tsplit2(pbx[i], pby[i], hi, lo);
                dBh[bws[i]] = hi;
                dBl[bws[i]] = lo;
            }
        }
        __syncthreads();
    }

    // ---- epilogue (verbatim) ----
#pragma unroll
    for (int mt = 0; mt < 4; mt++) {
#pragma unroll
        for (int half = 0; half < 2; half++) {
            int mrow = wm * 64 + mt * 16 + l4 + half * 8;
            if (m0 + mrow >= cnt) continue;
            if (G1) {
                float* hrow = g_h + (size_t)(off + m0 + mrow) * DFF_DIM + n0;
#pragma unroll
                for (int nt = 0; nt < 4; nt++) {
                    int c = wn * 32 + nt * 8 + lc * 2;
                    float v0 = gelu_exact(acc[mt][nt][half * 2 + 0] + bias[c]);
                    float v1 = gelu_exact(acc[mt][nt][half * 2 + 1] + bias[c + 1]);
                    *(float2*)(hrow + c) = make_float2(v0, v1);
                }
            } else {
                int tok = stok_s[mrow];
                float wgt = swgt_s[mrow];
                float* orow = out + (size_t)tok * C_DIM + n0;
#pragma unroll
                for (int nt = 0; nt < 4; nt++) {
                    int c = wn * 32 + nt * 8 + lc * 2;
                    atomicAdd(orow + c,     wgt * (acc[mt][nt][half * 2 + 0] + bias[c]));
                    atomicAdd(orow + c + 1, wgt * (acc[mt][nt][half * 2 + 1] + bias[c + 1]));
                }
            }
        }
    }
}

// ---------------- launch ------------------------------------------------------
extern "C" void kernel_launch(void* const* d_in, const int* in_sizes, int n_in,
                              void* d_out, int out_size) {
    const float* x  = (const float*)d_in[0];
    const float* rw = (const float*)d_in[1];
    const float* rb = (const float*)d_in[2];
    const float* w1 = (const float*)d_in[3];
    const float* b1 = (const float*)d_in[4];
    const float* w2 = (const float*)d_in[5];
    const float* b2 = (const float*)d_in[6];
    float* out = (float*)d_out;

    cudaFuncSetAttribute(gemm_hmma<C_DIM, DFF_DIM, true>,
                         cudaFuncAttributeMaxDynamicSharedMemorySize, SMEM_DYN_BYTES);
    cudaFuncSetAttribute(gemm_hmma<DFF_DIM, C_DIM, false>,
                         cudaFuncAttributeMaxDynamicSharedMemorySize, SMEM_DYN_BYTES);

    zero_counts_kernel<<<1, 32>>>();
    router_kernel<<<N_TOK, 128>>>(x, rw, rb);
    offsets_kernel<<<1, 1>>>();
    zero_out_kernel<<<512, 256>>>(out, N_TOK * C_DIM);

    {
        dim3 g(DFF_DIM / 128, N_TOK / 128, E_NUM);
        gemm_hmma<C_DIM, DFF_DIM, true><<<g, 256, SMEM_DYN_BYTES>>>(x, w1, b1, nullptr);
    }
    {
        dim3 g(C_DIM / 128, N_TOK / 128, E_NUM);
        gemm_hmma<DFF_DIM, C_DIM, false><<<g, 256, SMEM_DYN_BYTES>>>(nullptr, w2, b2, out);
    }
}

// round 14
// speedup vs baseline: 1.8861x; 1.0199x over previous
#include <cuda_runtime.h>
#include <cuda_bf16.h>
#include <cstdint>
#include <math.h>

#define N_TOK 8192
#define C_DIM 1024
#define E_NUM 8
#define DFF_DIM 4096
#define HROWS (2 * N_TOK + 128)

// ---------------- scratch (~270MB total — proven-passing level) ---------------
__device__ float g_h[HROWS * DFF_DIM];     // fp32 gelu(x@w1) rows, bucketed
__device__ int   g_counts[E_NUM];
__device__ int   g_offsets[E_NUM];
__device__ int   g_tok[E_NUM * N_TOK];
__device__ float g_wgt[E_NUM * N_TOK];

// ---------------- helpers -----------------------------------------------------
__device__ __forceinline__ void mma_bf16(float* d, const uint32_t* a, const uint32_t* b) {
    asm volatile(
        "mma.sync.aligned.m16n8k16.row.col.f32.bf16.bf16.f32 "
        "{%0,%1,%2,%3}, {%4,%5,%6,%7}, {%8,%9}, {%0,%1,%2,%3};"
        : "+f"(d[0]), "+f"(d[1]), "+f"(d[2]), "+f"(d[3])
        : "r"(a[0]), "r"(a[1]), "r"(a[2]), "r"(a[3]), "r"(b[0]), "r"(b[1]));
}

// truncation split of a pair: hi = top 16 bits (exact trunc), lo = exact residual
__device__ __forceinline__ void tsplit2(float vx, float vy, uint32_t& hi, uint32_t& lo) {
    uint32_t ax = __float_as_uint(vx), ay = __float_as_uint(vy);
    float lx = vx - __uint_as_float(ax & 0xFFFF0000u);
    float ly = vy - __uint_as_float(ay & 0xFFFF0000u);
    hi = __byte_perm(ax, ay, 0x7632);
    lo = __byte_perm(__float_as_uint(lx), __float_as_uint(ly), 0x7632);
}

__device__ __forceinline__ float gelu_exact(float v) {
    return 0.5f * v * (1.0f + erff(v * 0.70710678118654752f));
}

// ---------------- small kernels (verbatim) -------------------------------------
__global__ void zero_counts_kernel() {
    if (threadIdx.x < E_NUM) g_counts[threadIdx.x] = 0;
}
__global__ void zero_out_kernel(float* out, int n) {
    for (int i = blockIdx.x * blockDim.x + threadIdx.x; i < n; i += gridDim.x * blockDim.x)
        out[i] = 0.0f;
}
__global__ void offsets_kernel() {
    int run = 0;
    for (int e = 0; e < E_NUM; e++) { g_offsets[e] = run; run += g_counts[e]; }
}

__global__ void router_kernel(const float* __restrict__ x,
                              const float* __restrict__ rw,
                              const float* __restrict__ rb) {
    int t = blockIdx.x;
    int tid = threadIdx.x;
    __shared__ float red[128][E_NUM];
    float acc[E_NUM];
#pragma unroll
    for (int e = 0; e < E_NUM; e++) acc[e] = 0.0f;
    const float* xr = x + (size_t)t * C_DIM;
    for (int c = tid; c < C_DIM; c += 128) {
        float xv = xr[c];
        const float* w = &rw[c * E_NUM];
#pragma unroll
        for (int e = 0; e < E_NUM; e++) acc[e] += xv * w[e];
    }
#pragma unroll
    for (int e = 0; e < E_NUM; e++) red[tid][e] = acc[e];
    __syncthreads();
    for (int s = 64; s > 0; s >>= 1) {
        if (tid < s) {
#pragma unroll
            for (int e = 0; e < E_NUM; e++) red[tid][e] += red[tid + s][e];
        }
        __syncthreads();
    }
    if (tid == 0) {
        float lg[E_NUM], p[E_NUM];
        float mx = -1e30f;
#pragma unroll
        for (int e = 0; e < E_NUM; e++) { lg[e] = red[0][e] + rb[e]; mx = fmaxf(mx, lg[e]); }
        float sum = 0.0f;
#pragma unroll
        for (int e = 0; e < E_NUM; e++) { p[e] = expf(lg[e] - mx); sum += p[e]; }
        float inv = 1.0f / sum;
#pragma unroll
        for (int e = 0; e < E_NUM; e++) p[e] *= inv;
        int i1 = 0;
#pragma unroll
        for (int e = 1; e < E_NUM; e++) if (p[e] > p[i1]) i1 = e;
        int i2 = (i1 == 0) ? 1 : 0;
#pragma unroll
        for (int e = 0; e < E_NUM; e++) if (e != i1 && p[e] > p[i2]) i2 = e;
        int s1 = atomicAdd(&g_counts[i1], 1);
        g_tok[i1 * N_TOK + s1] = t;  g_wgt[i1 * N_TOK + s1] = p[i1];
        int s2 = atomicAdd(&g_counts[i2], 1);
        g_tok[i2 * N_TOK + s2] = t;  g_wgt[i2 * N_TOK + s2] = p[i2];
    }
}

// ---------------- HMMA GEMM: 64m x 128n CTA, 128 threads, occupancy 2 ----------
// 4 warps (1m x 4n), warp tile 64x32 (4 mt x 4 nt) — fragment math = round 10
// with wm = 0. Single-buffer stage k=32; 2 CTAs/SM overlap staging with MMA.
// A smem: [slice][row(64)][8 words] pitch 8 (conflict-free)
// B smem: [slice][n(128)][8 words] pitch 10 (conflict-free)
template <int KTOT, int NDIM, bool G1>
__global__ void __launch_bounds__(128, 2)
gemm_hmma(const float* __restrict__ A_g, const float* __restrict__ B_g,
          const float* __restrict__ bias_g, float* __restrict__ out) {
    __shared__ __align__(16) uint32_t sAh[2 * 64 * 8];
    __shared__ __align__(16) uint32_t sAl[2 * 64 * 8];
    __shared__ __align__(16) uint32_t sBh[2 * 128 * 10];
    __shared__ __align__(16) uint32_t sBl[2 * 128 * 10];
    __shared__ int   srow_s[64];
    __shared__ int   stok_s[64];
    __shared__ float swgt_s[64];

    int e = blockIdx.z;
    int cnt = g_counts[e];
    int m0 = blockIdx.y * 64;
    if (m0 >= cnt) return;
    int n0 = blockIdx.x * 128;
    int off = g_offsets[e];

    int tid = threadIdx.x, lane = tid & 31;
    int wn = tid >> 5;                  // 4 warps, all at wm = 0
    int l4 = lane >> 2, lc = lane & 3;

    if (tid < 64) {
        int m = m0 + tid;
        int sr = 0, tk = 0; float wg = 0.0f;
        if (m < cnt) {
            tk = g_tok[e * N_TOK + m];
            wg = g_wgt[e * N_TOK + m];
            sr = G1 ? tk : (off + m);
        }
        srow_s[tid] = sr; stok_s[tid] = tk; swgt_s[tid] = wg;
    }
    __syncthreads();

    const float* Abase = G1 ? A_g : g_h;
    const float* Bp = B_g + (size_t)e * KTOT * NDIM + n0;
    const float* bias = bias_g + (size_t)e * NDIM + n0;

    // ---- staging assignments ----
    // A: k-pair prA = tid&15, rows (tid>>4) + 8*i (i<8)  => 64 rows x 16 pairs
    int prA = tid & 15;
    int slA = prA >> 3, wA = prA & 7;
    int posA = (wA & 3) * 2 + (wA >> 2);
    const float* aptr[8];
    int aws0;
    {
        int rA = tid >> 4;
#pragma unroll
        for (int i = 0; i < 8; i++) {
            int r = rA + 8 * i;
            aptr[i] = Abase + (size_t)srow_s[r] * KTOT + 2 * prA;
        }
        aws0 = (slA * 64 + rA) * 8 + posA;   // +64 words per i
    }
    // B: col nB = tid (0..127), pairs pk = i (i<16)
    const float* bbase = Bp + tid;
    int bws_base = tid * 10;

    float acc[4][4][4];
#pragma unroll
    for (int a = 0; a < 4; a++)
#pragma unroll
        for (int b = 0; b < 4; b++)
#pragma unroll
            for (int c = 0; c < 4; c++) acc[a][b][c] = 0.0f;

    const int NS = KTOT / 32;
    for (int s = 0; s < NS; s++) {
        // ---- stage: LDG -> split -> STS (overlapped by the OTHER CTA's MMAs) ----
        size_t ka = (size_t)s * 32;
#pragma unroll
        for (int i = 0; i < 8; i++) {
            float2 v = *(const float2*)(aptr[i] + ka);
            uint32_t hi, lo;
            tsplit2(v.x, v.y, hi, lo);
            sAh[aws0 + 64 * i] = hi;
            sAl[aws0 + 64 * i] = lo;
        }
        {
            const float* bs = bbase + ka * NDIM;
#pragma unroll
            for (int i = 0; i < 16; i++) {
                float bx = bs[(size_t)(2 * i) * NDIM];
                float by = bs[(size_t)(2 * i + 1) * NDIM];
                uint32_t hi, lo;
                tsplit2(bx, by, hi, lo);
                int slB = i >> 3, wB = i & 7;
                int posB = (wB & 3) * 2 + (wB >> 2);
                sBh[slB * 1280 + bws_base + posB] = hi;
                sBl[slB * 1280 + bws_base + posB] = lo;
            }
        }
        __syncthreads();

        // ---- compute ----
#pragma unroll
        for (int ks = 0; ks < 2; ks++) {
            uint32_t bhf[4][2], blf[4][2];
#pragma unroll
            for (int nt = 0; nt < 4; nt++) {
                int n = wn * 32 + nt * 8 + l4;
                int wbi = (ks * 128 + n) * 10 + 2 * lc;
                uint2 h = *(const uint2*)&sBh[wbi];
                uint2 l = *(const uint2*)&sBl[wbi];
                bhf[nt][0] = h.x; bhf[nt][1] = h.y;
                blf[nt][0] = l.x; blf[nt][1] = l.y;
            }
#pragma unroll
            for (int mt = 0; mt < 4; mt++) {
                int r = mt * 16 + l4;
                int wa0 = (ks * 64 + r) * 8 + 2 * lc;
                int wa1 = (ks * 64 + r + 8) * 8 + 2 * lc;
                uint2 h0 = *(const uint2*)&sAh[wa0];
                uint2 h1 = *(const uint2*)&sAh[wa1];
                uint2 l0 = *(const uint2*)&sAl[wa0];
                uint2 l1 = *(const uint2*)&sAl[wa1];
                uint32_t ah[4] = {h0.x, h1.x, h0.y, h1.y};
                uint32_t al[4] = {l0.x, l1.x, l0.y, l1.y};
#pragma unroll
                for (int nt = 0; nt < 4; nt++) {
                    mma_bf16(acc[mt][nt], ah, bhf[nt]);
                    mma_bf16(acc[mt][nt], ah, blf[nt]);
                    mma_bf16(acc[mt][nt], al, bhf[nt]);
                }
            }
        }
        __syncthreads();
    }

    // ---- epilogue ----
#pragma unroll
    for (int mt = 0; mt < 4; mt++) {
#pragma unroll
        for (int half = 0; half < 2; half++) {
            int mrow = mt * 16 + l4 + half * 8;
            if (m0 + mrow >= cnt) continue;
            if (G1) {
                float* hrow = g_h + (size_t)(off + m0 + mrow) * DFF_DIM + n0;
#pragma unroll
                for (int nt = 0; nt < 4; nt++) {
                    int c = wn * 32 + nt * 8 + lc * 2;
                    float v0 = gelu_exact(acc[mt][nt][half * 2 + 0] + bias[c]);
                    float v1 = gelu_exact(acc[mt][nt][half * 2 + 1] + bias[c + 1]);
                    *(float2*)(hrow + c) = make_float2(v0, v1);
                }
            } else {
                int tok = stok_s[mrow];
                float wgt = swgt_s[mrow];
                float* orow = out + (size_t)tok * C_DIM + n0;
#pragma unroll
                for (int nt = 0; nt < 4; nt++) {
                    int c = wn * 32 + nt * 8 + lc * 2;
                    atomicAdd(orow + c,     wgt * (acc[mt][nt][half * 2 + 0] + bias[c]));
                    atomicAdd(orow + c + 1, wgt * (acc[mt][nt][half * 2 + 1] + bias[c + 1]));
                }
            }
        }
    }
}

// ---------------- launch ------------------------------------------------------
extern "C" void kernel_launch(void* const* d_in, const int* in_sizes, int n_in,
                              void* d_out, int out_size) {
    const float* x  = (const float*)d_in[0];
    const float* rw = (const float*)d_in[1];
    const float* rb = (const float*)d_in[2];
    const float* w1 = (const float*)d_in[3];
    const float* b1 = (const float*)d_in[4];
    const float* w2 = (const float*)d_in[5];
    const float* b2 = (const float*)d_in[6];
    float* out = (float*)d_out;

    zero_counts_kernel<<<1, 32>>>();
    router_kernel<<<N_TOK, 128>>>(x, rw, rb);
    offsets_kernel<<<1, 1>>>();
    zero_out_kernel<<<512, 256>>>(out, N_TOK * C_DIM);

    {
        dim3 g(DFF_DIM / 128, N_TOK / 64, E_NUM);
        gemm_hmma<C_DIM, DFF_DIM, true><<<g, 128>>>(x, w1, b1, nullptr);
    }
    {
        dim3 g(C_DIM / 128, N_TOK / 64, E_NUM);
        gemm_hmma<DFF_DIM, C_DIM, false><<<g, 128>>>(nullptr, w2, b2, out);
    }
}